// round 3
// baseline (speedup 1.0000x reference)
#include <cuda_runtime.h>

#define TRACES 4096
#define LSEQ   64
#define ISZ    64
#define HSZ    128
#define RBLK   256            // reduction stage-1 blocks (16 traces each)

typedef unsigned long long ull;

// Scratch (static device globals — no allocation).
__device__ float g_trace_emb[TRACES * HSZ];
__device__ float g_partial[RBLK * HSZ];

// Shared memory layout (float offsets)
#define OFF_X   0                       // [64][64]   gathered embeddings
#define OFF_H1  4096                    // [64][128]  layer-1 hidden
#define OFF_H2  12288                   // [64][128]  layer-2 hidden
#define OFF_W   20480                   // [128][132] staged weight tile
#define OFF_E   (20480 + 128*132)       // [64]       energies / softmax weights
#define SMEM_FLOATS (OFF_E + 64)
#define WSTRIDE 132                     // conflict-free LDS.128 (4-bank skew)

// ---- packed f32x2 FMA (FFMA2) ----
__device__ __forceinline__ void fma2(ull& d, ull a, ull b) {
    asm("fma.rn.f32x2 %0, %1, %2, %0;" : "+l"(d) : "l"(a), "l"(b));
}
__device__ __forceinline__ float sum2(ull v) {
    union { ull u; float2 f; } c; c.u = v;
    return c.f.x + c.f.y;
}
__device__ __forceinline__ float tanh_ap(float x) {
    float y; asm("tanh.approx.f32 %0, %1;" : "=f"(y) : "f"(x)); return y;
}
__device__ __forceinline__ float sigm(float x) {
    return fmaf(0.5f, tanh_ap(0.5f * x), 0.5f);
}

// Cooperatively stage a [128 x K] weight block into sW with padded stride.
template <int K>
__device__ __forceinline__ void stage_w(const float* __restrict__ g, float* sW, int t) {
    constexpr int NF4 = 128 * K / 4;
#pragma unroll
    for (int q = 0; q < NF4 / 512; q++) {
        int fid = q * 512 + t;
        int r = fid / (K / 4);
        int c = (fid % (K / 4)) * 4;
        *(float4*)(sW + r * WSTRIDE + c) = *(const float4*)(g + r * K + c);
    }
}

// 2(rows) x 8(tokens) micro-tile with packed f32x2 accumulators.
// Lane j covers gate rows {rh*64+j, rh*64+j+32}; tokens t0..t0+7.
// W LDS bytes per fma2 halved vs a 4x4 tile (token reuse 8).
template <int K>
__device__ __forceinline__ void mm_accum2(const float* __restrict__ sIn,
                                          const float* __restrict__ sW,
                                          int j, int rh, int t0, ull acc[2][8]) {
#pragma unroll 4
    for (int kk = 0; kk < K; kk += 8) {
        ulonglong2 wA[2], wB[2];
#pragma unroll
        for (int m = 0; m < 2; m++) {
            const float* wr = sW + (rh * 64 + j + 32 * m) * WSTRIDE + kk;
            wA[m] = *(const ulonglong2*)wr;
            wB[m] = *(const ulonglong2*)(wr + 4);
        }
#pragma unroll
        for (int tt = 0; tt < 8; tt++) {
            const float* xr = sIn + (t0 + tt) * K + kk;   // broadcast across lanes
            ulonglong2 xA = *(const ulonglong2*)xr;
            ulonglong2 xB = *(const ulonglong2*)(xr + 4);
#pragma unroll
            for (int m = 0; m < 2; m++) {
                fma2(acc[m][tt], wA[m].x, xA.x);
                fma2(acc[m][tt], wA[m].y, xA.y);
                fma2(acc[m][tt], wB[m].x, xB.x);
                fma2(acc[m][tt], wB[m].y, xB.y);
            }
        }
    }
}

// One LSTM layer from zero state. Gate rows: i=[0,128), f dead, c_hat=[256,384),
// o=[384,512). Activation folded per stage to cap register pressure.
template <int K>
__device__ __forceinline__ void lstm_layer(const float* __restrict__ sIn,
                                           float* __restrict__ sOut,
                                           float* __restrict__ sW,
                                           const float* __restrict__ W,
                                           const float* __restrict__ bi,
                                           const float* __restrict__ bh,
                                           int t) {
    const int j  = t & 31;
    const int w  = t >> 5;
    const int rh = w & 1;            // which 64-row half of the gate
    const int t0 = (w >> 1) * 8;     // token group (8 tokens)
    float carry[2][8];               // s0: sigmoid(i); s1: c

#pragma unroll
    for (int s = 0; s < 3; s++) {
        const int base = (s == 0) ? 0 : (s == 1) ? 2 * HSZ : 3 * HSZ;
        __syncthreads();                       // protect sW from prior readers
        stage_w<K>(W + base * K, sW, t);
        __syncthreads();

        ull acc[2][8];
#pragma unroll
        for (int m = 0; m < 2; m++)
#pragma unroll
            for (int tt = 0; tt < 8; tt++) acc[m][tt] = 0ULL;

        mm_accum2<K>(sIn, sW, j, rh, t0, acc);

#pragma unroll
        for (int m = 0; m < 2; m++) {
            int row = rh * 64 + j + 32 * m;
            int g = base + row;
            float b = bi[g] + bh[g];
#pragma unroll
            for (int tt = 0; tt < 8; tt++) {
                float v = sum2(acc[m][tt]) + b;
                if (s == 0) {
                    carry[m][tt] = sigm(v);
                } else if (s == 1) {
                    carry[m][tt] = carry[m][tt] * tanh_ap(v);
                } else {
                    sOut[(t0 + tt) * HSZ + row] = sigm(v) * tanh_ap(carry[m][tt]);
                }
            }
        }
    }
}

__global__ __launch_bounds__(512, 1) void fused_trace_kernel(
    const float* __restrict__ emb,
    const float* __restrict__ W1,
    const float* __restrict__ bi1, const float* __restrict__ bh1,
    const float* __restrict__ W2,
    const float* __restrict__ bi2, const float* __restrict__ bh2,
    const float* __restrict__ Wp1, const float* __restrict__ bp1,
    const float* __restrict__ Wp2, const float* __restrict__ bp2,
    const int* __restrict__ traces, const int* __restrict__ lengths)
{
    extern __shared__ float sm[];
    const int t = threadIdx.x;
    const int trace = blockIdx.x;

    // ---- Gather token embeddings: X[64][64] ----
    {
        int l = t >> 3;
        int seg = t & 7;
        int id = traces[trace * LSEQ + l];
        const float4* src = (const float4*)(emb + id * ISZ + seg * 8);
        float4* dst = (float4*)(sm + OFF_X + l * ISZ + seg * 8);
        dst[0] = src[0];
        dst[1] = src[1];
    }
    // first __syncthreads inside lstm_layer covers visibility

    lstm_layer<ISZ>(sm + OFF_X, sm + OFF_H1, sm + OFF_W, W1, bi1, bh1, t);
    lstm_layer<HSZ>(sm + OFF_H1, sm + OFF_H2, sm + OFF_W, W2, bi2, bh2, t);

    // ---- Attention MLP: energy[l] = relu(h2 @ Wp1^T + bp1) @ Wp2^T + bp2 ----
    __syncthreads();
    {   // stage Wp1 [64 x 128]
#pragma unroll
        for (int q = 0; q < 4; q++) {
            int fid = q * 512 + t;
            int r = fid >> 5;
            int c = (fid & 31) * 4;
            *(float4*)(sm + OFF_W + r * WSTRIDE + c) = *(const float4*)(Wp1 + r * HSZ + c);
        }
    }
    __syncthreads();
    {
        const int token = t >> 3;
        const int pi = t & 7;
        ull accp[8];
#pragma unroll
        for (int m = 0; m < 8; m++) accp[m] = 0ULL;
#pragma unroll 4
        for (int kk = 0; kk < HSZ; kk += 8) {
            const float* hr = sm + OFF_H2 + token * HSZ + kk;
            ulonglong2 hA = *(const ulonglong2*)hr;
            ulonglong2 hB = *(const ulonglong2*)(hr + 4);
#pragma unroll
            for (int m = 0; m < 8; m++) {
                const float* wr = sm + OFF_W + (pi + 8 * m) * WSTRIDE + kk;
                ulonglong2 wA = *(const ulonglong2*)wr;
                ulonglong2 wB = *(const ulonglong2*)(wr + 4);
                fma2(accp[m], wA.x, hA.x);
                fma2(accp[m], wA.y, hA.y);
                fma2(accp[m], wB.x, hB.x);
                fma2(accp[m], wB.y, hB.y);
            }
        }
        float partial = 0.f;
#pragma unroll
        for (int m = 0; m < 8; m++) {
            float pv = sum2(accp[m]) + bp1[pi + 8 * m];
            pv = fmaxf(pv, 0.f);
            partial = fmaf(pv, Wp2[pi + 8 * m], partial);
        }
        partial += __shfl_down_sync(0xffffffffu, partial, 4, 8);
        partial += __shfl_down_sync(0xffffffffu, partial, 2, 8);
        partial += __shfl_down_sync(0xffffffffu, partial, 1, 8);
        if (pi == 0) sm[OFF_E + token] = partial + bp2[0];
    }
    __syncthreads();

    // ---- Masked softmax over 64 positions (warp 0) ----
    if (t < 32) {
        int len = lengths[trace];
        float v0 = (t      < len) ? sm[OFF_E + t]      : -1e30f;
        float v1 = (t + 32 < len) ? sm[OFF_E + t + 32] : -1e30f;
        float mx = fmaxf(v0, v1);
#pragma unroll
        for (int off = 16; off > 0; off >>= 1)
            mx = fmaxf(mx, __shfl_xor_sync(0xffffffffu, mx, off));
        float e0 = __expf(v0 - mx);
        float e1 = __expf(v1 - mx);
        float ss = e0 + e1;
#pragma unroll
        for (int off = 16; off > 0; off >>= 1)
            ss += __shfl_xor_sync(0xffffffffu, ss, off);
        float inv = __fdividef(1.0f, ss);
        sm[OFF_E + t]      = e0 * inv;
        sm[OFF_E + t + 32] = e1 * inv;
    }
    __syncthreads();

    // ---- Weighted sum over positions -> per-trace embedding ----
    if (t < HSZ) {
        float acc = 0.f;
#pragma unroll 4
        for (int l = 0; l < LSEQ; l++)
            acc = fmaf(sm[OFF_E + l], sm[OFF_H2 + l * HSZ + t], acc);
        g_trace_emb[trace * HSZ + t] = acc;
    }
}

// Stage-1 reduction: 256 blocks, each sums 16 traces (deterministic partition).
__global__ __launch_bounds__(128) void reduce_part_kernel() {
    const int b = blockIdx.x;
    const int t = threadIdx.x;
    float s = 0.f;
    const int tr0 = b * (TRACES / RBLK);
#pragma unroll
    for (int i = 0; i < TRACES / RBLK; i++)
        s += g_trace_emb[(tr0 + i) * HSZ + t];
    g_partial[b * HSZ + t] = s;
}

// Stage-2: sum partials + final 128x128 matvec.
__global__ __launch_bounds__(128) void reduce_out_kernel(
    const float* __restrict__ Wout, const float* __restrict__ bout,
    float* __restrict__ out)
{
    __shared__ float sfinal[HSZ];
    const int t = threadIdx.x;
    float s = 0.f;
#pragma unroll 8
    for (int p = 0; p < RBLK; p++)
        s += g_partial[p * HSZ + t];
    sfinal[t] = s;
    __syncthreads();
    float o = bout[t];
#pragma unroll 4
    for (int h = 0; h < HSZ; h++)
        o = fmaf(Wout[t * HSZ + h], sfinal[h], o);
    out[t] = o;
}

extern "C" void kernel_launch(void* const* d_in, const int* in_sizes, int n_in,
                              void* d_out, int out_size) {
    const float* emb    = (const float*)d_in[0];
    const float* W1     = (const float*)d_in[1];
    const float* bi1    = (const float*)d_in[3];
    const float* bh1    = (const float*)d_in[4];
    const float* W2     = (const float*)d_in[5];
    const float* bi2    = (const float*)d_in[7];
    const float* bh2    = (const float*)d_in[8];
    const float* Wp1    = (const float*)d_in[9];
    const float* bp1    = (const float*)d_in[10];
    const float* Wp2    = (const float*)d_in[11];
    const float* bp2    = (const float*)d_in[12];
    const float* Wout   = (const float*)d_in[13];
    const float* bout   = (const float*)d_in[14];
    const int*   traces = (const int*)d_in[15];
    const int*   lens   = (const int*)d_in[16];

    cudaFuncSetAttribute(fused_trace_kernel,
                         cudaFuncAttributeMaxDynamicSharedMemorySize,
                         SMEM_FLOATS * sizeof(float));

    fused_trace_kernel<<<TRACES, 512, SMEM_FLOATS * sizeof(float)>>>(
        emb, W1, bi1, bh1, W2, bi2, bh2, Wp1, bp1, Wp2, bp2, traces, lens);

    reduce_part_kernel<<<RBLK, 128>>>();
    reduce_out_kernel<<<1, 128>>>(Wout, bout, (float*)d_out);
}

// round 4
// speedup vs baseline: 1.0036x; 1.0036x over previous
#include <cuda_runtime.h>

#define TRACES 4096
#define LSEQ   64
#define ISZ    64
#define HSZ    128
#define RBLK   256            // reduction stage-1 blocks (16 traces each)

typedef unsigned long long ull;

// Scratch (static device globals — no allocation).
__device__ float g_trace_emb[TRACES * HSZ];
__device__ float g_partial[RBLK * HSZ];

// Shared memory layout (float offsets)
#define OFF_X   0                       // [64][64]   gathered embeddings
#define OFF_H1  4096                    // [64][128]  layer-1 hidden
#define OFF_H2  12288                   // [64][128]  layer-2 hidden
#define OFF_W   20480                   // [128][132] staged weight tile
#define OFF_E   (20480 + 128*132)       // [64]       energies / softmax weights
#define SMEM_FLOATS (OFF_E + 64)
#define WSTRIDE 132                     // conflict-free LDS.128 (4-bank skew)

// ---- packed f32x2 FMA (FFMA2) ----
__device__ __forceinline__ void fma2(ull& d, ull a, ull b) {
    asm("fma.rn.f32x2 %0, %1, %2, %0;" : "+l"(d) : "l"(a), "l"(b));
}
__device__ __forceinline__ float sum2(ull v) {
    union { ull u; float2 f; } c; c.u = v;
    return c.f.x + c.f.y;
}
__device__ __forceinline__ float tanh_ap(float x) {
    float y; asm("tanh.approx.f32 %0, %1;" : "=f"(y) : "f"(x)); return y;
}
__device__ __forceinline__ float sigm(float x) {
    return fmaf(0.5f, tanh_ap(0.5f * x), 0.5f);
}

// Cooperatively stage a [128 x K] weight block into sW with padded stride.
template <int K>
__device__ __forceinline__ void stage_w(const float* __restrict__ g, float* sW, int t) {
    constexpr int NF4 = 128 * K / 4;
#pragma unroll
    for (int q = 0; q < NF4 / 512; q++) {
        int fid = q * 512 + t;
        int r = fid / (K / 4);
        int c = (fid % (K / 4)) * 4;
        *(float4*)(sW + r * WSTRIDE + c) = *(const float4*)(g + r * K + c);
    }
}

// 2(rows) x 8(tokens) micro-tile with packed f32x2 accumulators.
// Lane j covers gate rows {rh*64+j, rh*64+j+32}; tokens t0..t0+7.
// W LDS bytes per fma2 halved vs a 4x4 tile (token reuse 8).
template <int K>
__device__ __forceinline__ void mm_accum2(const float* __restrict__ sIn,
                                          const float* __restrict__ sW,
                                          int j, int rh, int t0, ull acc[2][8]) {
#pragma unroll 4
    for (int kk = 0; kk < K; kk += 8) {
        ulonglong2 wA[2], wB[2];
#pragma unroll
        for (int m = 0; m < 2; m++) {
            const float* wr = sW + (rh * 64 + j + 32 * m) * WSTRIDE + kk;
            wA[m] = *(const ulonglong2*)wr;
            wB[m] = *(const ulonglong2*)(wr + 4);
        }
#pragma unroll
        for (int tt = 0; tt < 8; tt++) {
            const float* xr = sIn + (t0 + tt) * K + kk;   // broadcast across lanes
            ulonglong2 xA = *(const ulonglong2*)xr;
            ulonglong2 xB = *(const ulonglong2*)(xr + 4);
#pragma unroll
            for (int m = 0; m < 2; m++) {
                fma2(acc[m][tt], wA[m].x, xA.x);
                fma2(acc[m][tt], wA[m].y, xA.y);
                fma2(acc[m][tt], wB[m].x, xB.x);
                fma2(acc[m][tt], wB[m].y, xB.y);
            }
        }
    }
}

// One LSTM layer from zero state. Gate rows: i=[0,128), f dead, c_hat=[256,384),
// o=[384,512). Activation folded per stage to cap register pressure.
template <int K>
__device__ __forceinline__ void lstm_layer(const float* __restrict__ sIn,
                                           float* __restrict__ sOut,
                                           float* __restrict__ sW,
                                           const float* __restrict__ W,
                                           const float* __restrict__ bi,
                                           const float* __restrict__ bh,
                                           int t) {
    const int j  = t & 31;
    const int w  = t >> 5;
    const int rh = w & 1;            // which 64-row half of the gate
    const int t0 = (w >> 1) * 8;     // token group (8 tokens)
    float carry[2][8];               // s0: sigmoid(i); s1: c

#pragma unroll
    for (int s = 0; s < 3; s++) {
        const int base = (s == 0) ? 0 : (s == 1) ? 2 * HSZ : 3 * HSZ;
        __syncthreads();                       // protect sW from prior readers
        stage_w<K>(W + base * K, sW, t);
        __syncthreads();

        ull acc[2][8];
#pragma unroll
        for (int m = 0; m < 2; m++)
#pragma unroll
            for (int tt = 0; tt < 8; tt++) acc[m][tt] = 0ULL;

        mm_accum2<K>(sIn, sW, j, rh, t0, acc);

#pragma unroll
        for (int m = 0; m < 2; m++) {
            int row = rh * 64 + j + 32 * m;
            int g = base + row;
            float b = bi[g] + bh[g];
#pragma unroll
            for (int tt = 0; tt < 8; tt++) {
                float v = sum2(acc[m][tt]) + b;
                if (s == 0) {
                    carry[m][tt] = sigm(v);
                } else if (s == 1) {
                    carry[m][tt] = carry[m][tt] * tanh_ap(v);
                } else {
                    sOut[(t0 + tt) * HSZ + row] = sigm(v) * tanh_ap(carry[m][tt]);
                }
            }
        }
    }
}

__global__ __launch_bounds__(512, 1) void fused_trace_kernel(
    const float* __restrict__ emb,
    const float* __restrict__ W1,
    const float* __restrict__ bi1, const float* __restrict__ bh1,
    const float* __restrict__ W2,
    const float* __restrict__ bi2, const float* __restrict__ bh2,
    const float* __restrict__ Wp1, const float* __restrict__ bp1,
    const float* __restrict__ Wp2, const float* __restrict__ bp2,
    const int* __restrict__ traces, const int* __restrict__ lengths)
{
    extern __shared__ float sm[];
    const int t = threadIdx.x;
    const int trace = blockIdx.x;

    // ---- Gather token embeddings: X[64][64] ----
    {
        int l = t >> 3;
        int seg = t & 7;
        int id = traces[trace * LSEQ + l];
        const float4* src = (const float4*)(emb + id * ISZ + seg * 8);
        float4* dst = (float4*)(sm + OFF_X + l * ISZ + seg * 8);
        dst[0] = src[0];
        dst[1] = src[1];
    }
    // first __syncthreads inside lstm_layer covers visibility

    lstm_layer<ISZ>(sm + OFF_X, sm + OFF_H1, sm + OFF_W, W1, bi1, bh1, t);
    lstm_layer<HSZ>(sm + OFF_H1, sm + OFF_H2, sm + OFF_W, W2, bi2, bh2, t);

    // ---- Attention MLP: energy[l] = relu(h2 @ Wp1^T + bp1) @ Wp2^T + bp2 ----
    __syncthreads();
    {   // stage Wp1 [64 x 128]
#pragma unroll
        for (int q = 0; q < 4; q++) {
            int fid = q * 512 + t;
            int r = fid >> 5;
            int c = (fid & 31) * 4;
            *(float4*)(sm + OFF_W + r * WSTRIDE + c) = *(const float4*)(Wp1 + r * HSZ + c);
        }
    }
    __syncthreads();
    {
        const int token = t >> 3;
        const int pi = t & 7;
        ull accp[8];
#pragma unroll
        for (int m = 0; m < 8; m++) accp[m] = 0ULL;
#pragma unroll 4
        for (int kk = 0; kk < HSZ; kk += 8) {
            const float* hr = sm + OFF_H2 + token * HSZ + kk;
            ulonglong2 hA = *(const ulonglong2*)hr;
            ulonglong2 hB = *(const ulonglong2*)(hr + 4);
#pragma unroll
            for (int m = 0; m < 8; m++) {
                const float* wr = sm + OFF_W + (pi + 8 * m) * WSTRIDE + kk;
                ulonglong2 wA = *(const ulonglong2*)wr;
                ulonglong2 wB = *(const ulonglong2*)(wr + 4);
                fma2(accp[m], wA.x, hA.x);
                fma2(accp[m], wA.y, hA.y);
                fma2(accp[m], wB.x, hB.x);
                fma2(accp[m], wB.y, hB.y);
            }
        }
        float partial = 0.f;
#pragma unroll
        for (int m = 0; m < 8; m++) {
            float pv = sum2(accp[m]) + bp1[pi + 8 * m];
            pv = fmaxf(pv, 0.f);
            partial = fmaf(pv, Wp2[pi + 8 * m], partial);
        }
        partial += __shfl_down_sync(0xffffffffu, partial, 4, 8);
        partial += __shfl_down_sync(0xffffffffu, partial, 2, 8);
        partial += __shfl_down_sync(0xffffffffu, partial, 1, 8);
        if (pi == 0) sm[OFF_E + token] = partial + bp2[0];
    }
    __syncthreads();

    // ---- Masked softmax over 64 positions (warp 0) ----
    if (t < 32) {
        int len = lengths[trace];
        float v0 = (t      < len) ? sm[OFF_E + t]      : -1e30f;
        float v1 = (t + 32 < len) ? sm[OFF_E + t + 32] : -1e30f;
        float mx = fmaxf(v0, v1);
#pragma unroll
        for (int off = 16; off > 0; off >>= 1)
            mx = fmaxf(mx, __shfl_xor_sync(0xffffffffu, mx, off));
        float e0 = __expf(v0 - mx);
        float e1 = __expf(v1 - mx);
        float ss = e0 + e1;
#pragma unroll
        for (int off = 16; off > 0; off >>= 1)
            ss += __shfl_xor_sync(0xffffffffu, ss, off);
        float inv = __fdividef(1.0f, ss);
        sm[OFF_E + t]      = e0 * inv;
        sm[OFF_E + t + 32] = e1 * inv;
    }
    __syncthreads();

    // ---- Weighted sum over positions -> per-trace embedding ----
    if (t < HSZ) {
        float acc = 0.f;
#pragma unroll 4
        for (int l = 0; l < LSEQ; l++)
            acc = fmaf(sm[OFF_E + l], sm[OFF_H2 + l * HSZ + t], acc);
        g_trace_emb[trace * HSZ + t] = acc;
    }
}

// Stage-1 reduction: 256 blocks, each sums 16 traces (deterministic partition).
__global__ __launch_bounds__(128) void reduce_part_kernel() {
    const int b = blockIdx.x;
    const int t = threadIdx.x;
    float s = 0.f;
    const int tr0 = b * (TRACES / RBLK);
#pragma unroll
    for (int i = 0; i < TRACES / RBLK; i++)
        s += g_trace_emb[(tr0 + i) * HSZ + t];
    g_partial[b * HSZ + t] = s;
}

// Stage-2: sum partials + final 128x128 matvec.
__global__ __launch_bounds__(128) void reduce_out_kernel(
    const float* __restrict__ Wout, const float* __restrict__ bout,
    float* __restrict__ out)
{
    __shared__ float sfinal[HSZ];
    const int t = threadIdx.x;
    float s = 0.f;
#pragma unroll 8
    for (int p = 0; p < RBLK; p++)
        s += g_partial[p * HSZ + t];
    sfinal[t] = s;
    __syncthreads();
    float o = bout[t];
#pragma unroll 4
    for (int h = 0; h < HSZ; h++)
        o = fmaf(Wout[t * HSZ + h], sfinal[h], o);
    out[t] = o;
}

extern "C" void kernel_launch(void* const* d_in, const int* in_sizes, int n_in,
                              void* d_out, int out_size) {
    const float* emb    = (const float*)d_in[0];
    const float* W1     = (const float*)d_in[1];
    const float* bi1    = (const float*)d_in[3];
    const float* bh1    = (const float*)d_in[4];
    const float* W2     = (const float*)d_in[5];
    const float* bi2    = (const float*)d_in[7];
    const float* bh2    = (const float*)d_in[8];
    const float* Wp1    = (const float*)d_in[9];
    const float* bp1    = (const float*)d_in[10];
    const float* Wp2    = (const float*)d_in[11];
    const float* bp2    = (const float*)d_in[12];
    const float* Wout   = (const float*)d_in[13];
    const float* bout   = (const float*)d_in[14];
    const int*   traces = (const int*)d_in[15];
    const int*   lens   = (const int*)d_in[16];

    cudaFuncSetAttribute(fused_trace_kernel,
                         cudaFuncAttributeMaxDynamicSharedMemorySize,
                         SMEM_FLOATS * sizeof(float));

    fused_trace_kernel<<<TRACES, 512, SMEM_FLOATS * sizeof(float)>>>(
        emb, W1, bi1, bh1, W2, bi2, bh2, Wp1, bp1, Wp2, bp2, traces, lens);

    reduce_part_kernel<<<RBLK, 128>>>();
    reduce_out_kernel<<<1, 128>>>(Wout, bout, (float*)d_out);
}

// round 6
// speedup vs baseline: 5.3391x; 5.3201x over previous
#include <cuda_runtime.h>
#include <cuda_bf16.h>
#include <cstdint>

#define TRACES 4096
#define LSEQ   64
#define HSZ    128
#define RBLK   256

typedef unsigned int uint;

// ---- device scratch (static globals, no allocation) ----
__device__ uint2 g_fw1[3 * 16 * 4 * 32];   // [gate][ntile][k16][lane]
__device__ uint2 g_fw2[3 * 16 * 8 * 32];
__device__ uint2 g_fwp[8 * 8 * 32];
__device__ float g_trace_emb[TRACES * HSZ];
__device__ float g_partial[RBLK * HSZ];

// ---- smem byte layout ----
#define S_X    0            // X  [64 tok][72 bf16]  stride 144B (9216B)
#define S_H1   9216         // h1 [64][136 bf16]     stride 272B (17408B)
#define S_H2   26624        // h2 [64][136 bf16]     stride 272B (17408B)
#define S_E    44032        // 64 floats
#define SMEM_BYTES 44288
#define CBUF   S_H1         // MLP contrib reuse: [64 tok][68 f32] stride 272B

__device__ __forceinline__ uint32_t smem_u32(const void* p) {
    uint32_t a;
    asm("{ .reg .u64 t; cvta.to.shared.u64 t, %1; cvt.u32.u64 %0, t; }" : "=r"(a) : "l"(p));
    return a;
}
__device__ __forceinline__ uint lds32(uint32_t a) {
    uint v; asm volatile("ld.shared.b32 %0, [%1];" : "=r"(v) : "r"(a)); return v;
}
__device__ __forceinline__ void sts32(uint32_t a, uint v) {
    asm volatile("st.shared.b32 [%0], %1;" :: "r"(a), "r"(v));
}
__device__ __forceinline__ void sts64f(uint32_t a, float x, float y) {
    asm volatile("st.shared.v2.f32 [%0], {%1, %2};" :: "r"(a), "f"(x), "f"(y));
}
__device__ __forceinline__ void mma16816(float c[4], const uint a[4], uint b0, uint b1) {
    asm volatile(
        "mma.sync.aligned.m16n8k16.row.col.f32.bf16.bf16.f32 "
        "{%0,%1,%2,%3}, {%4,%5,%6,%7}, {%8,%9}, {%0,%1,%2,%3};"
        : "+f"(c[0]), "+f"(c[1]), "+f"(c[2]), "+f"(c[3])
        : "r"(a[0]), "r"(a[1]), "r"(a[2]), "r"(a[3]), "r"(b0), "r"(b1));
}
__device__ __forceinline__ float tanh_ap(float x) {
    float y; asm("tanh.approx.f32 %0, %1;" : "=f"(y) : "f"(x)); return y;
}
__device__ __forceinline__ float sigm(float x) {
    return fmaf(0.5f, tanh_ap(0.5f * x), 0.5f);
}
__device__ __forceinline__ uint pack_bf2(float a, float b) {
    __nv_bfloat162 t = __float22bfloat162_rn(make_float2(a, b));
    return *reinterpret_cast<uint*>(&t);
}

// ---------------- init: pack W into mma B-fragment layout ----------------
// B frag (m16n8k16, row.col): b0 = {B[k0][n], B[k0+1][n]}, b1 = {+8}, with
// n = ntile*8 + (lane>>2), k0 = k16*16 + (lane&3)*2.  Gate rows: i=0, c=256, o=384.
__global__ void init_frags(const float* __restrict__ W1, const float* __restrict__ W2,
                           const float* __restrict__ Wp1) {
    int idx = blockIdx.x * 256 + threadIdx.x;
    const int GR[3] = {0, 256, 384};
    if (idx < 6144) {                       // L1: [3][16][4][32], K=64
        int lane = idx & 31, k16 = (idx >> 5) & 3, nt = (idx >> 7) & 15, g = idx >> 11;
        int n = nt * 8 + (lane >> 2), k0 = k16 * 16 + (lane & 3) * 2;
        const float* r = W1 + (GR[g] + n) * 64;
        g_fw1[idx] = make_uint2(pack_bf2(r[k0], r[k0 + 1]),
                                pack_bf2(r[k0 + 8], r[k0 + 9]));
    } else if (idx < 18432) {               // L2: [3][16][8][32], K=128
        int j = idx - 6144;
        int lane = j & 31, k16 = (j >> 5) & 7, nt = (j >> 8) & 15, g = j >> 12;
        int n = nt * 8 + (lane >> 2), k0 = k16 * 16 + (lane & 3) * 2;
        const float* r = W2 + (GR[g] + n) * 128;
        g_fw2[j] = make_uint2(pack_bf2(r[k0], r[k0 + 1]),
                              pack_bf2(r[k0 + 8], r[k0 + 9]));
    } else if (idx < 20480) {               // MLP: [8][8][32], K=128, R=64
        int j = idx - 18432;
        int lane = j & 31, k16 = (j >> 5) & 7, nt = j >> 8;
        int n = nt * 8 + (lane >> 2), k0 = k16 * 16 + (lane & 3) * 2;
        const float* r = Wp1 + n * 128;
        g_fwp[j] = make_uint2(pack_bf2(r[k0], r[k0 + 1]),
                              pack_bf2(r[k0 + 8], r[k0 + 9]));
    }
}

// ---------------- fused per-trace kernel ----------------
// Warp w owns n-tiles {2w, 2w+1} (gate rows 16w..16w+15) x all 4 m-tiles (tokens).
template <int K16>
__device__ __forceinline__ void lstm_layer_mma(
    uint32_t inA, int istride, uint32_t outH,
    const uint2* __restrict__ frag,
    const float* __restrict__ bi, const float* __restrict__ bh,
    int w, int lane)
{
    const int gid = lane >> 2, tig = lane & 3;
    float carry[4][2][4];

#pragma unroll
    for (int s = 0; s < 3; s++) {
        const int RB = (s == 0) ? 0 : (s == 1) ? 256 : 384;
        float acc[4][2][4];
#pragma unroll
        for (int m = 0; m < 4; m++)
#pragma unroll
            for (int n2 = 0; n2 < 2; n2++)
#pragma unroll
                for (int j = 0; j < 4; j++) acc[m][n2][j] = 0.f;

#pragma unroll
        for (int k = 0; k < K16; k++) {
            uint a[4][4];
#pragma unroll
            for (int m = 0; m < 4; m++) {
                uint32_t base = inA + (m * 16 + gid) * istride + k * 32 + tig * 4;
                a[m][0] = lds32(base);
                a[m][1] = lds32(base + 8 * istride);
                a[m][2] = lds32(base + 16);
                a[m][3] = lds32(base + 8 * istride + 16);
            }
#pragma unroll
            for (int n2 = 0; n2 < 2; n2++) {
                uint2 b = __ldg(&frag[(((s * 16) + (2 * w + n2)) * K16 + k) * 32 + lane]);
#pragma unroll
                for (int m = 0; m < 4; m++) mma16816(acc[m][n2], a[m], b.x, b.y);
            }
        }

#pragma unroll
        for (int n2 = 0; n2 < 2; n2++) {
            const int col0 = (2 * w + n2) * 8 + tig * 2;
            const float b0 = bi[RB + col0] + bh[RB + col0];
            const float b1 = bi[RB + col0 + 1] + bh[RB + col0 + 1];
#pragma unroll
            for (int m = 0; m < 4; m++) {
                float v0 = acc[m][n2][0] + b0;
                float v1 = acc[m][n2][1] + b1;
                float v2 = acc[m][n2][2] + b0;
                float v3 = acc[m][n2][3] + b1;
                if (s == 0) {
                    carry[m][n2][0] = sigm(v0); carry[m][n2][1] = sigm(v1);
                    carry[m][n2][2] = sigm(v2); carry[m][n2][3] = sigm(v3);
                } else if (s == 1) {
                    carry[m][n2][0] *= tanh_ap(v0); carry[m][n2][1] *= tanh_ap(v1);
                    carry[m][n2][2] *= tanh_ap(v2); carry[m][n2][3] *= tanh_ap(v3);
                } else {
                    const int tok0 = m * 16 + gid;
                    float h0 = sigm(v0) * tanh_ap(carry[m][n2][0]);
                    float h1 = sigm(v1) * tanh_ap(carry[m][n2][1]);
                    float h2 = sigm(v2) * tanh_ap(carry[m][n2][2]);
                    float h3 = sigm(v3) * tanh_ap(carry[m][n2][3]);
                    sts32(outH + tok0 * 272 + col0 * 2, pack_bf2(h0, h1));
                    sts32(outH + (tok0 + 8) * 272 + col0 * 2, pack_bf2(h2, h3));
                }
            }
        }
    }
}

__global__ __launch_bounds__(256, 2) void fused_mma_kernel(
    const float* __restrict__ emb,
    const float* __restrict__ bi1, const float* __restrict__ bh1,
    const float* __restrict__ bi2, const float* __restrict__ bh2,
    const float* __restrict__ bp1, const float* __restrict__ bp2,
    const float* __restrict__ wp2,
    const int* __restrict__ traces, const int* __restrict__ lengths)
{
    extern __shared__ char smc[];
    const int tid = threadIdx.x, w = tid >> 5, lane = tid & 31;
    const int gid = lane >> 2, tig = lane & 3;
    const int trace = blockIdx.x;
    const uint32_t sb = smem_u32(smc);

    // ---- gather X -> bf16 smem [64 tok][stride 144B] ----
    {
        int tok = tid >> 2, seg = tid & 3;
        int id = traces[trace * LSEQ + tok];
        const float4* s = (const float4*)(emb + id * 64 + seg * 16);
        float4 f0 = s[0], f1 = s[1], f2 = s[2], f3 = s[3];
        uint4 c0, c1;
        c0.x = pack_bf2(f0.x, f0.y); c0.y = pack_bf2(f0.z, f0.w);
        c0.z = pack_bf2(f1.x, f1.y); c0.w = pack_bf2(f1.z, f1.w);
        c1.x = pack_bf2(f2.x, f2.y); c1.y = pack_bf2(f2.z, f2.w);
        c1.z = pack_bf2(f3.x, f3.y); c1.w = pack_bf2(f3.z, f3.w);
        *(uint4*)(smc + S_X + tok * 144 + seg * 32) = c0;
        *(uint4*)(smc + S_X + tok * 144 + seg * 32 + 16) = c1;
    }
    __syncthreads();

    // ---- LSTM layers ----
    lstm_layer_mma<4>(sb + S_X, 144, sb + S_H1, g_fw1, bi1, bh1, w, lane);
    __syncthreads();
    lstm_layer_mma<8>(sb + S_H1, 272, sb + S_H2, g_fw2, bi2, bh2, w, lane);
    __syncthreads();

    // ---- MLP energy GEMM: D[64 tok][64 p], warp w owns n-tile w ----
    {
        float acc[4][4];
#pragma unroll
        for (int m = 0; m < 4; m++)
#pragma unroll
            for (int j = 0; j < 4; j++) acc[m][j] = 0.f;
#pragma unroll
        for (int k = 0; k < 8; k++) {
            uint a[4][4];
#pragma unroll
            for (int m = 0; m < 4; m++) {
                uint32_t base = sb + S_H2 + (m * 16 + gid) * 272 + k * 32 + tig * 4;
                a[m][0] = lds32(base);
                a[m][1] = lds32(base + 8 * 272);
                a[m][2] = lds32(base + 16);
                a[m][3] = lds32(base + 8 * 272 + 16);
            }
            uint2 b = __ldg(&g_fwp[(w * 8 + k) * 32 + lane]);
#pragma unroll
            for (int m = 0; m < 4; m++) mma16816(acc[m], a[m], b.x, b.y);
        }
        // contrib[tok][p] = relu(v + bp1[p]) * wp2[p]  (h1 buffer reused as cbuf)
        const int p0 = w * 8 + tig * 2;
        const float bb0 = bp1[p0], bb1 = bp1[p0 + 1];
        const float w20 = wp2[p0], w21 = wp2[p0 + 1];
        __syncthreads();   // all h1 reads done (layer-2 finished earlier)
#pragma unroll
        for (int m = 0; m < 4; m++) {
            const int tok0 = m * 16 + gid;
            float v0 = fmaxf(acc[m][0] + bb0, 0.f) * w20;
            float v1 = fmaxf(acc[m][1] + bb1, 0.f) * w21;
            float v2 = fmaxf(acc[m][2] + bb0, 0.f) * w20;
            float v3 = fmaxf(acc[m][3] + bb1, 0.f) * w21;
            sts64f(sb + CBUF + tok0 * 272 + p0 * 4, v0, v1);
            sts64f(sb + CBUF + (tok0 + 8) * 272 + p0 * 4, v2, v3);
        }
    }
    __syncthreads();

    // ---- energy reduce over p ----
    float* E = (float*)(smc + S_E);
    if (tid < 64) {
        const float* row = (const float*)(smc + CBUF + tid * 272);
        float s = 0.f;
#pragma unroll 8
        for (int p = 0; p < 64; p++) s += row[p];
        E[tid] = s + bp2[0];
    }
    __syncthreads();

    // ---- masked softmax (warp 0) ----
    if (tid < 32) {
        int len = lengths[trace];
        float v0 = (tid      < len) ? E[tid]      : -1e30f;
        float v1 = (tid + 32 < len) ? E[tid + 32] : -1e30f;
        float mx = fmaxf(v0, v1);
#pragma unroll
        for (int o = 16; o > 0; o >>= 1) mx = fmaxf(mx, __shfl_xor_sync(~0u, mx, o));
        float e0 = __expf(v0 - mx), e1 = __expf(v1 - mx);
        float ss = e0 + e1;
#pragma unroll
        for (int o = 16; o > 0; o >>= 1) ss += __shfl_xor_sync(~0u, ss, o);
        float inv = __fdividef(1.f, ss);
        E[tid] = e0 * inv; E[tid + 32] = e1 * inv;
    }
    __syncthreads();

    // ---- weighted sum over positions (thread = 2 dims via bf16x2 word) ----
    if (tid < 64) {
        float ax = 0.f, ay = 0.f;
#pragma unroll 4
        for (int l = 0; l < LSEQ; l++) {
            uint hw = lds32(sb + S_H2 + l * 272 + tid * 4);
            __nv_bfloat162 hv = *reinterpret_cast<__nv_bfloat162*>(&hw);
            float e = E[l];
            ax = fmaf(e, __bfloat162float(hv.x), ax);
            ay = fmaf(e, __bfloat162float(hv.y), ay);
        }
        g_trace_emb[trace * HSZ + 2 * tid]     = ax;
        g_trace_emb[trace * HSZ + 2 * tid + 1] = ay;
    }
}

// ---------------- deterministic reduction + output matvec ----------------
__global__ __launch_bounds__(128) void reduce_part_kernel() {
    const int b = blockIdx.x, t = threadIdx.x;
    float s = 0.f;
    const int tr0 = b * (TRACES / RBLK);
#pragma unroll
    for (int i = 0; i < TRACES / RBLK; i++)
        s += g_trace_emb[(tr0 + i) * HSZ + t];
    g_partial[b * HSZ + t] = s;
}

__global__ __launch_bounds__(128) void reduce_out_kernel(
    const float* __restrict__ Wout, const float* __restrict__ bout,
    float* __restrict__ out)
{
    __shared__ float sfinal[HSZ];
    const int t = threadIdx.x;
    float s = 0.f;
#pragma unroll 8
    for (int p = 0; p < RBLK; p++) s += g_partial[p * HSZ + t];
    sfinal[t] = s;
    __syncthreads();
    float o = bout[t];
#pragma unroll 4
    for (int h = 0; h < HSZ; h++) o = fmaf(Wout[t * HSZ + h], sfinal[h], o);
    out[t] = o;
}

extern "C" void kernel_launch(void* const* d_in, const int* in_sizes, int n_in,
                              void* d_out, int out_size) {
    const float* emb    = (const float*)d_in[0];
    const float* W1     = (const float*)d_in[1];
    const float* bi1    = (const float*)d_in[3];
    const float* bh1    = (const float*)d_in[4];
    const float* W2     = (const float*)d_in[5];
    const float* bi2    = (const float*)d_in[7];
    const float* bh2    = (const float*)d_in[8];
    const float* Wp1    = (const float*)d_in[9];
    const float* bp1    = (const float*)d_in[10];
    const float* Wp2    = (const float*)d_in[11];
    const float* bp2    = (const float*)d_in[12];
    const float* Wout   = (const float*)d_in[13];
    const float* bout   = (const float*)d_in[14];
    const int*   traces = (const int*)d_in[15];
    const int*   lens   = (const int*)d_in[16];

    cudaFuncSetAttribute(fused_mma_kernel,
                         cudaFuncAttributeMaxDynamicSharedMemorySize, SMEM_BYTES);

    init_frags<<<80, 256>>>(W1, W2, Wp1);
    fused_mma_kernel<<<TRACES, 256, SMEM_BYTES>>>(
        emb, bi1, bh1, bi2, bh2, bp1, bp2, Wp2, traces, lens);
    reduce_part_kernel<<<RBLK, 128>>>();
    reduce_out_kernel<<<1, 128>>>(Wout, bout, (float*)d_out);
}

// round 7
// speedup vs baseline: 7.3159x; 1.3703x over previous
#include <cuda_runtime.h>
#include <cuda_bf16.h>
#include <cstdint>

#define TRACES 4096
#define LSEQ   64
#define HSZ    128
#define RBLK   256

typedef unsigned int uint;

// ---- device scratch (static globals, no allocation) ----
__device__ uint2 g_fw1[3 * 16 * 4 * 32];   // [gate][ntile][k16][lane]
__device__ uint2 g_fw2[3 * 16 * 8 * 32];
__device__ uint2 g_fwp[8 * 8 * 32];
__device__ float g_trace_emb[TRACES * HSZ];
__device__ float g_partial[RBLK * HSZ];

// ---- smem byte layout ----
#define S_X    0            // X  [64 tok][72 bf16]  stride 144B (9216B)
#define S_H1   9216         // h1 [64][136 bf16]     stride 272B (17408B)
#define S_H2   26624        // h2 [64][136 bf16]     stride 272B (17408B)
#define S_E    44032        // 64 floats
#define SMEM_BYTES 44288
#define CBUF   S_H1         // MLP contrib reuse: [64 tok][68 f32] stride 272B

__device__ __forceinline__ uint32_t smem_u32(const void* p) {
    uint32_t a;
    asm("{ .reg .u64 t; cvta.to.shared.u64 t, %1; cvt.u32.u64 %0, t; }" : "=r"(a) : "l"(p));
    return a;
}
__device__ __forceinline__ uint lds32(uint32_t a) {
    uint v; asm volatile("ld.shared.b32 %0, [%1];" : "=r"(v) : "r"(a)); return v;
}
__device__ __forceinline__ void sts32(uint32_t a, uint v) {
    asm volatile("st.shared.b32 [%0], %1;" :: "r"(a), "r"(v));
}
__device__ __forceinline__ void sts64f(uint32_t a, float x, float y) {
    asm volatile("st.shared.v2.f32 [%0], {%1, %2};" :: "r"(a), "f"(x), "f"(y));
}
__device__ __forceinline__ void ldsm4(uint r[4], uint32_t addr) {
    asm volatile("ldmatrix.sync.aligned.m8n8.x4.shared.b16 {%0,%1,%2,%3}, [%4];"
                 : "=r"(r[0]), "=r"(r[1]), "=r"(r[2]), "=r"(r[3]) : "r"(addr));
}
__device__ __forceinline__ void mma16816(float c[4], const uint a[4], uint b0, uint b1) {
    asm volatile(
        "mma.sync.aligned.m16n8k16.row.col.f32.bf16.bf16.f32 "
        "{%0,%1,%2,%3}, {%4,%5,%6,%7}, {%8,%9}, {%0,%1,%2,%3};"
        : "+f"(c[0]), "+f"(c[1]), "+f"(c[2]), "+f"(c[3])
        : "r"(a[0]), "r"(a[1]), "r"(a[2]), "r"(a[3]), "r"(b0), "r"(b1));
}
__device__ __forceinline__ float tanh_ap(float x) {
    float y; asm("tanh.approx.f32 %0, %1;" : "=f"(y) : "f"(x)); return y;
}
__device__ __forceinline__ float sigm(float x) {
    return fmaf(0.5f, tanh_ap(0.5f * x), 0.5f);
}
__device__ __forceinline__ uint pack_bf2(float a, float b) {
    __nv_bfloat162 t = __float22bfloat162_rn(make_float2(a, b));
    return *reinterpret_cast<uint*>(&t);
}

// ---------------- init: pack W into mma B-fragment layout ----------------
// B frag (m16n8k16, row.col): b0 = {B[k0][n], B[k0+1][n]}, b1 = {+8}, with
// n = ntile*8 + (lane>>2), k0 = k16*16 + (lane&3)*2.  Gate rows: i=0, c=256, o=384.
__global__ void init_frags(const float* __restrict__ W1, const float* __restrict__ W2,
                           const float* __restrict__ Wp1) {
    int idx = blockIdx.x * 256 + threadIdx.x;
    const int GR[3] = {0, 256, 384};
    if (idx < 6144) {                       // L1: [3][16][4][32], K=64
        int lane = idx & 31, k16 = (idx >> 5) & 3, nt = (idx >> 7) & 15, g = idx >> 11;
        int n = nt * 8 + (lane >> 2), k0 = k16 * 16 + (lane & 3) * 2;
        const float* r = W1 + (GR[g] + n) * 64;
        g_fw1[idx] = make_uint2(pack_bf2(r[k0], r[k0 + 1]),
                                pack_bf2(r[k0 + 8], r[k0 + 9]));
    } else if (idx < 18432) {               // L2: [3][16][8][32], K=128
        int j = idx - 6144;
        int lane = j & 31, k16 = (j >> 5) & 7, nt = (j >> 8) & 15, g = j >> 12;
        int n = nt * 8 + (lane >> 2), k0 = k16 * 16 + (lane & 3) * 2;
        const float* r = W2 + (GR[g] + n) * 128;
        g_fw2[j] = make_uint2(pack_bf2(r[k0], r[k0 + 1]),
                              pack_bf2(r[k0 + 8], r[k0 + 9]));
    } else if (idx < 20480) {               // MLP: [8][8][32], K=128, R=64
        int j = idx - 18432;
        int lane = j & 31, k16 = (j >> 5) & 7, nt = j >> 8;
        int n = nt * 8 + (lane >> 2), k0 = k16 * 16 + (lane & 3) * 2;
        const float* r = Wp1 + n * 128;
        g_fwp[j] = make_uint2(pack_bf2(r[k0], r[k0 + 1]),
                              pack_bf2(r[k0 + 8], r[k0 + 9]));
    }
}

// ---------------- fused per-trace kernel ----------------
// Warp w owns n-tiles {2w, 2w+1} (gate rows 16w..16w+15) x MT m-tiles (tokens).
// ldmatrix row offset: lanes 0-15 rows 0-15, lanes 16-31 same rows cols +8.
template <int K16, int MT>
__device__ __forceinline__ void lstm_layer_mma(
    uint32_t inA, int istride, uint32_t outH,
    const uint2* __restrict__ frag,
    const float* __restrict__ bi, const float* __restrict__ bh,
    int w, int lane)
{
    const int gid = lane >> 2, tig = lane & 3;
    const uint32_t rowoff = (uint32_t)((lane & 15) * istride + ((lane & 16) ? 16 : 0));
    float carry[MT][2][4];

#pragma unroll
    for (int s = 0; s < 3; s++) {
        const int RB = (s == 0) ? 0 : (s == 1) ? 256 : 384;
        float acc[MT][2][4];
#pragma unroll
        for (int m = 0; m < MT; m++)
#pragma unroll
            for (int n2 = 0; n2 < 2; n2++)
#pragma unroll
                for (int j = 0; j < 4; j++) acc[m][n2][j] = 0.f;

#pragma unroll
        for (int k = 0; k < K16; k++) {
            uint a[MT][4];
#pragma unroll
            for (int m = 0; m < MT; m++)
                ldsm4(a[m], inA + (uint32_t)(m * 16 * istride + k * 32) + rowoff);
#pragma unroll
            for (int n2 = 0; n2 < 2; n2++) {
                uint2 b = __ldg(&frag[(((s * 16) + (2 * w + n2)) * K16 + k) * 32 + lane]);
#pragma unroll
                for (int m = 0; m < MT; m++) mma16816(acc[m][n2], a[m], b.x, b.y);
            }
        }

#pragma unroll
        for (int n2 = 0; n2 < 2; n2++) {
            const int col0 = (2 * w + n2) * 8 + tig * 2;
            const float b0 = bi[RB + col0] + bh[RB + col0];
            const float b1 = bi[RB + col0 + 1] + bh[RB + col0 + 1];
#pragma unroll
            for (int m = 0; m < MT; m++) {
                float v0 = acc[m][n2][0] + b0;
                float v1 = acc[m][n2][1] + b1;
                float v2 = acc[m][n2][2] + b0;
                float v3 = acc[m][n2][3] + b1;
                if (s == 0) {
                    carry[m][n2][0] = sigm(v0); carry[m][n2][1] = sigm(v1);
                    carry[m][n2][2] = sigm(v2); carry[m][n2][3] = sigm(v3);
                } else if (s == 1) {
                    carry[m][n2][0] *= tanh_ap(v0); carry[m][n2][1] *= tanh_ap(v1);
                    carry[m][n2][2] *= tanh_ap(v2); carry[m][n2][3] *= tanh_ap(v3);
                } else {
                    const int tok0 = m * 16 + gid;
                    float h0 = sigm(v0) * tanh_ap(carry[m][n2][0]);
                    float h1 = sigm(v1) * tanh_ap(carry[m][n2][1]);
                    float h2 = sigm(v2) * tanh_ap(carry[m][n2][2]);
                    float h3 = sigm(v3) * tanh_ap(carry[m][n2][3]);
                    sts32(outH + tok0 * 272 + col0 * 2, pack_bf2(h0, h1));
                    sts32(outH + (tok0 + 8) * 272 + col0 * 2, pack_bf2(h2, h3));
                }
            }
        }
    }
}

template <int MT>
__device__ __forceinline__ void trace_compute(
    char* smc, uint32_t sb, int w, int lane,
    const float* __restrict__ bi1, const float* __restrict__ bh1,
    const float* __restrict__ bi2, const float* __restrict__ bh2,
    const float* __restrict__ bp1, const float* __restrict__ wp2)
{
    const int gid = lane >> 2, tig = lane & 3;

    lstm_layer_mma<4, MT>(sb + S_X, 144, sb + S_H1, g_fw1, bi1, bh1, w, lane);
    __syncthreads();
    lstm_layer_mma<8, MT>(sb + S_H1, 272, sb + S_H2, g_fw2, bi2, bh2, w, lane);
    __syncthreads();

    // ---- MLP energy GEMM: D[MT*16 tok][64 p], warp w owns n-tile w ----
    float acc[MT][4];
#pragma unroll
    for (int m = 0; m < MT; m++)
#pragma unroll
        for (int j = 0; j < 4; j++) acc[m][j] = 0.f;
    const uint32_t rowoff = (uint32_t)((lane & 15) * 272 + ((lane & 16) ? 16 : 0));
#pragma unroll
    for (int k = 0; k < 8; k++) {
        uint a[MT][4];
#pragma unroll
        for (int m = 0; m < MT; m++)
            ldsm4(a[m], sb + S_H2 + (uint32_t)(m * 16 * 272 + k * 32) + rowoff);
        uint2 b = __ldg(&g_fwp[(w * 8 + k) * 32 + lane]);
#pragma unroll
        for (int m = 0; m < MT; m++) mma16816(acc[m], a[m], b.x, b.y);
    }
    // contrib[tok][p] = relu(v + bp1[p]) * wp2[p]  (h1 buffer reused as cbuf)
    const int p0 = w * 8 + tig * 2;
    const float bb0 = bp1[p0], bb1 = bp1[p0 + 1];
    const float w20 = wp2[p0], w21 = wp2[p0 + 1];
    __syncthreads();   // all h1 reads done
#pragma unroll
    for (int m = 0; m < MT; m++) {
        const int tok0 = m * 16 + gid;
        float v0 = fmaxf(acc[m][0] + bb0, 0.f) * w20;
        float v1 = fmaxf(acc[m][1] + bb1, 0.f) * w21;
        float v2 = fmaxf(acc[m][2] + bb0, 0.f) * w20;
        float v3 = fmaxf(acc[m][3] + bb1, 0.f) * w21;
        sts64f(sb + CBUF + tok0 * 272 + p0 * 4, v0, v1);
        sts64f(sb + CBUF + (tok0 + 8) * 272 + p0 * 4, v2, v3);
    }
}

__global__ __launch_bounds__(256, 2) void fused_mma_kernel(
    const float* __restrict__ emb,
    const float* __restrict__ bi1, const float* __restrict__ bh1,
    const float* __restrict__ bi2, const float* __restrict__ bh2,
    const float* __restrict__ bp1, const float* __restrict__ bp2,
    const float* __restrict__ wp2,
    const int* __restrict__ traces, const int* __restrict__ lengths)
{
    extern __shared__ char smc[];
    const int tid = threadIdx.x, w = tid >> 5, lane = tid & 31;
    const int trace = blockIdx.x;
    const uint32_t sb = smem_u32(smc);
    const int len = lengths[trace];

    // ---- gather X -> bf16 smem [64 tok][stride 144B] ----
    {
        int tok = tid >> 2, seg = tid & 3;
        int id = traces[trace * LSEQ + tok];
        const float4* s = (const float4*)(emb + id * 64 + seg * 16);
        float4 f0 = s[0], f1 = s[1], f2 = s[2], f3 = s[3];
        uint4 c0, c1;
        c0.x = pack_bf2(f0.x, f0.y); c0.y = pack_bf2(f0.z, f0.w);
        c0.z = pack_bf2(f1.x, f1.y); c0.w = pack_bf2(f1.z, f1.w);
        c1.x = pack_bf2(f2.x, f2.y); c1.y = pack_bf2(f2.z, f2.w);
        c1.z = pack_bf2(f3.x, f3.y); c1.w = pack_bf2(f3.z, f3.w);
        *(uint4*)(smc + S_X + tok * 144 + seg * 32) = c0;
        *(uint4*)(smc + S_X + tok * 144 + seg * 32 + 16) = c1;
    }
    __syncthreads();

    // ---- length-specialized LSTM + MLP (only m-tiles covering len) ----
    const int mt = (len + 15) >> 4;
    switch (mt) {
        case 1: trace_compute<1>(smc, sb, w, lane, bi1, bh1, bi2, bh2, bp1, wp2); break;
        case 2: trace_compute<2>(smc, sb, w, lane, bi1, bh1, bi2, bh2, bp1, wp2); break;
        case 3: trace_compute<3>(smc, sb, w, lane, bi1, bh1, bi2, bh2, bp1, wp2); break;
        default: trace_compute<4>(smc, sb, w, lane, bi1, bh1, bi2, bh2, bp1, wp2); break;
    }
    __syncthreads();

    // ---- energy reduce over p (only valid tokens needed) ----
    float* E = (float*)(smc + S_E);
    if (tid < len) {
        const float* row = (const float*)(smc + CBUF + tid * 272);
        float s = 0.f;
#pragma unroll 8
        for (int p = 0; p < 64; p++) s += row[p];
        E[tid] = s + bp2[0];
    }
    __syncthreads();

    // ---- masked softmax (warp 0) ----
    if (tid < 32) {
        float v0 = (tid      < len) ? E[tid]      : -1e30f;
        float v1 = (tid + 32 < len) ? E[tid + 32] : -1e30f;
        float mx = fmaxf(v0, v1);
#pragma unroll
        for (int o = 16; o > 0; o >>= 1) mx = fmaxf(mx, __shfl_xor_sync(~0u, mx, o));
        float e0 = __expf(v0 - mx), e1 = __expf(v1 - mx);
        float ss = e0 + e1;
#pragma unroll
        for (int o = 16; o > 0; o >>= 1) ss += __shfl_xor_sync(~0u, ss, o);
        float inv = __fdividef(1.f, ss);
        E[tid] = e0 * inv; E[tid + 32] = e1 * inv;
    }
    __syncthreads();

    // ---- weighted sum over valid positions (thread = 2 dims, bf16x2 word) ----
    if (tid < 64) {
        float ax = 0.f, ay = 0.f;
#pragma unroll 4
        for (int l = 0; l < len; l++) {
            uint hw = lds32(sb + S_H2 + l * 272 + tid * 4);
            __nv_bfloat162 hv = *reinterpret_cast<__nv_bfloat162*>(&hw);
            float e = E[l];
            ax = fmaf(e, __bfloat162float(hv.x), ax);
            ay = fmaf(e, __bfloat162float(hv.y), ay);
        }
        g_trace_emb[trace * HSZ + 2 * tid]     = ax;
        g_trace_emb[trace * HSZ + 2 * tid + 1] = ay;
    }
}

// ---------------- deterministic reduction + output matvec ----------------
__global__ __launch_bounds__(128) void reduce_part_kernel() {
    const int b = blockIdx.x, t = threadIdx.x;
    float s = 0.f;
    const int tr0 = b * (TRACES / RBLK);
#pragma unroll
    for (int i = 0; i < TRACES / RBLK; i++)
        s += g_trace_emb[(tr0 + i) * HSZ + t];
    g_partial[b * HSZ + t] = s;
}

// 512 threads: 4 groups of 64 partials each, then combine + matvec.
__global__ __launch_bounds__(512) void reduce_out_kernel(
    const float* __restrict__ Wout, const float* __restrict__ bout,
    float* __restrict__ out)
{
    __shared__ float sq[512];
    __shared__ float sfinal[HSZ];
    const int tid = threadIdx.x;
    const int q = tid >> 7, h = tid & 127;
    float s = 0.f;
#pragma unroll 16
    for (int i = 0; i < RBLK / 4; i++)
        s += g_partial[(q * (RBLK / 4) + i) * HSZ + h];
    sq[tid] = s;
    __syncthreads();
    if (tid < HSZ)
        sfinal[tid] = sq[tid] + sq[128 + tid] + sq[256 + tid] + sq[384 + tid];
    __syncthreads();
    if (tid < HSZ) {
        float o = bout[tid];
#pragma unroll 8
        for (int k = 0; k < HSZ; k++)
            o = fmaf(__ldg(&Wout[tid * HSZ + k]), sfinal[k], o);
        out[tid] = o;
    }
}

extern "C" void kernel_launch(void* const* d_in, const int* in_sizes, int n_in,
                              void* d_out, int out_size) {
    const float* emb    = (const float*)d_in[0];
    const float* W1     = (const float*)d_in[1];
    const float* bi1    = (const float*)d_in[3];
    const float* bh1    = (const float*)d_in[4];
    const float* W2     = (const float*)d_in[5];
    const float* bi2    = (const float*)d_in[7];
    const float* bh2    = (const float*)d_in[8];
    const float* Wp1    = (const float*)d_in[9];
    const float* bp1    = (const float*)d_in[10];
    const float* Wp2    = (const float*)d_in[11];
    const float* bp2    = (const float*)d_in[12];
    const float* Wout   = (const float*)d_in[13];
    const float* bout   = (const float*)d_in[14];
    const int*   traces = (const int*)d_in[15];
    const int*   lens   = (const int*)d_in[16];

    cudaFuncSetAttribute(fused_mma_kernel,
                         cudaFuncAttributeMaxDynamicSharedMemorySize, SMEM_BYTES);

    init_frags<<<80, 256>>>(W1, W2, Wp1);
    fused_mma_kernel<<<TRACES, 256, SMEM_BYTES>>>(
        emb, bi1, bh1, bi2, bh2, bp1, bp2, Wp2, traces, lens);
    reduce_part_kernel<<<RBLK, 128>>>();
    reduce_out_kernel<<<1, 512>>>(Wout, bout, (float*)d_out);
}